// round 16
// baseline (speedup 1.0000x reference)
#include <cuda_runtime.h>
#include <cuda_fp16.h>
#include <cstdint>

// ---------------------------------------------------------------------------
// AttentionEncoderLayer: B=4, C=8, F=2048, H=512, NH=8, dh=64, Hf=1024
// Folded attention algebra (softmax shift-invariance + linearity):
//   scores: s_h[m,c] = (Qp_h[m] @ Wk_h) . k[8m+c]        (bk drops out)
//   values: x_h[m]   = (sum_c att_c v[8m+c]) @ Wv_h^T    (bv -> output bias)
// GEMMs: 1-pass fp16 HMMA (fp32 accum).
// This round: gemm_std at 512 threads / warp tile 32x32 (acc 32 regs) ->
// 32 warps/SM (2x), attacking the measured latency-bound regime
// (tensor 37.6%, L1 41%, nothing saturated, occ capped by regs).
// gemm_qt (persistent), gemm_n64, attn, LN unchanged from R13 best.
// ---------------------------------------------------------------------------

#define M_Q   8192
#define Hdim  512
#define HF    1024

typedef __half f16;

// fp32 spine
__device__ float g_x  [M_Q * Hdim];
__device__ float g_h1 [M_Q * Hdim];

// fp16 buffers
__device__ f16 g_q16 [M_Q * Hdim];
__device__ f16 g_Qp16[M_Q * Hdim];
__device__ f16 g_Qt  [M_Q * 8 * Hdim];     // [m, h*512+d]
__device__ f16 g_Y2  [8 * M_Q * Hdim];     // [h*8192+m, d]
__device__ f16 g_x16 [M_Q * Hdim];
__device__ f16 g_h1h [M_Q * Hdim];
__device__ f16 g_f1h [M_Q * HF  ];
__device__ f16 g_wq16[Hdim * Hdim];
__device__ f16 g_wkT [Hdim * Hdim];        // Wk transposed
__device__ f16 g_wv16[Hdim * Hdim];
__device__ f16 g_wo16[Hdim * Hdim];
__device__ f16 g_w116[HF * Hdim];
__device__ f16 g_w216[Hdim * HF];

// ---------------- helpers ----------------
__device__ __forceinline__ uint32_t smem_u32(const void* p) {
    uint32_t a;
    asm("{ .reg .u64 t; cvta.to.shared.u64 t, %1; cvt.u32.u64 %0, t; }" : "=r"(a) : "l"(p));
    return a;
}
__device__ __forceinline__ void ldsm4(uint32_t* r, uint32_t addr) {
    asm volatile("ldmatrix.sync.aligned.m8n8.x4.shared.b16 {%0,%1,%2,%3}, [%4];"
                 : "=r"(r[0]), "=r"(r[1]), "=r"(r[2]), "=r"(r[3]) : "r"(addr));
}
__device__ __forceinline__ void mma16816(float* d, const uint32_t* a, const uint32_t* b) {
    asm volatile("mma.sync.aligned.m16n8k16.row.col.f32.f16.f16.f32 "
                 "{%0,%1,%2,%3}, {%4,%5,%6,%7}, {%8,%9}, {%0,%1,%2,%3};"
                 : "+f"(d[0]), "+f"(d[1]), "+f"(d[2]), "+f"(d[3])
                 : "r"(a[0]), "r"(a[1]), "r"(a[2]), "r"(a[3]), "r"(b[0]), "r"(b[1]));
}
__device__ __forceinline__ void cp16(uint32_t dst, const void* src) {
    asm volatile("cp.async.cg.shared.global [%0], [%1], 16;" :: "r"(dst), "l"(src));
}
#define CP_COMMIT() asm volatile("cp.async.commit_group;" ::: "memory")
#define CP_WAIT1()  asm volatile("cp.async.wait_group 1;" ::: "memory")
#define CP_WAIT0()  asm volatile("cp.async.wait_group 0;" ::: "memory")

// ---------------------------------------------------------------------------
// prepass: fp32 -> fp16 (R13 layout: 5-job weight batch + plain query cvt)
// ---------------------------------------------------------------------------
struct CvtTbl {
    const float4* src[6];
    uint2*        dst[6];
    int           cum[6];
    int           njobs;
};

__global__ __launch_bounds__(256)
void cvt_batch(CvtTbl tbl)
{
    int i = blockIdx.x * 256 + threadIdx.x;
    if (i >= tbl.cum[tbl.njobs - 1]) return;
    int j = 0;
#pragma unroll
    for (int q = 0; q < 5; q++) if (j < tbl.njobs - 1 && i >= tbl.cum[j]) j++;
    const int base = (j == 0) ? 0 : tbl.cum[j - 1];
    const int idx = i - base;
    const float4 x = tbl.src[j][idx];
    __half2 h01 = __floats2half2_rn(x.x, x.y);
    __half2 h23 = __floats2half2_rn(x.z, x.w);
    tbl.dst[j][idx] = make_uint2(*(uint32_t*)&h01, *(uint32_t*)&h23);
}

__global__ __launch_bounds__(256)
void cvt_h16(const float4* __restrict__ src, uint2* __restrict__ hi, int n4)
{
    const int i = blockIdx.x * 256 + threadIdx.x;
    if (i >= n4) return;
    const float4 x = src[i];
    __half2 h01 = __floats2half2_rn(x.x, x.y);
    __half2 h23 = __floats2half2_rn(x.z, x.w);
    hi[i] = make_uint2(*(uint32_t*)&h01, *(uint32_t*)&h23);
}

// dst[c, r] = src[r, c]
__global__ __launch_bounds__(256)
void cvt_t16(const float* __restrict__ src, f16* __restrict__ dst, int R, int C)
{
    __shared__ float t[32][33];
    const int bi = blockIdx.x * 32, bj = blockIdx.y * 32;
    const int tx = threadIdx.x & 31, ty = threadIdx.x >> 5;
#pragma unroll
    for (int i = 0; i < 32; i += 8)
        t[ty + i][tx] = src[(size_t)(bi + ty + i) * C + bj + tx];
    __syncthreads();
#pragma unroll
    for (int i = 0; i < 32; i += 8)
        dst[(size_t)(bj + ty + i) * R + bi + tx] = __float2half_rn(t[tx][ty + i]);
}

// ---------------------------------------------------------------------------
// tile copiers (swizzled, 16B cp.async)
// ---------------------------------------------------------------------------
#define A_OFF 0
#define B_OFF 16384
#define BUF_STRIDE 32768
#define SMEM_GEMM (3 * BUF_STRIDE)   // 98304

// 256-thread copier (gemm_qt / gemm_n64)
__device__ __forceinline__ void cpa_tile(uint32_t dst, const f16* __restrict__ src,
                                         int ldk, int row0, int k0, int tid, int nrows)
{
    const int s  = tid & 7;
    const int r0 = tid >> 3;
    const char* g = (const char*)(src + (size_t)(row0 + r0) * ldk + k0) + s * 16;
    const uint32_t d0 = dst + r0 * 128 + ((s * 16) ^ ((r0 & 7) << 4));
    const size_t gs = (size_t)32 * ldk * 2;
#pragma unroll
    for (int i = 0; i < nrows / 32; i++)
        cp16(d0 + i * 32 * 128, g + i * gs);
}

// 512-thread copier (gemm_std): r0 covers 64 rows per pass
__device__ __forceinline__ void cpa_tile512(uint32_t dst, const f16* __restrict__ src,
                                            int ldk, int row0, int k0, int tid, int nrows)
{
    const int s  = tid & 7;
    const int r0 = tid >> 3;                 // 0..63
    const char* g = (const char*)(src + (size_t)(row0 + r0) * ldk + k0) + s * 16;
    const uint32_t d0 = dst + r0 * 128 + ((s * 16) ^ ((r0 & 7) << 4));
    const size_t gs = (size_t)64 * ldk * 2;
#pragma unroll
    for (int i = 0; i < nrows / 64; i++)
        cp16(d0 + i * 64 * 128, g + i * gs);
}

// ---------------------------------------------------------------------------
// std GEMM: C[m,n] = sum_k A[m,k]*B[n,k] + bias[n] (+res[m,n])
// BM=128 BN=128 BK=64, 512 threads / 16 warps (4m x 4n, warp tile 32x32),
// 3-stage cp.async, 2 CTAs/SM -> 32 warps/SM.
// ---------------------------------------------------------------------------
__global__ __launch_bounds__(512, 2)
void gemm_std(const f16* __restrict__ A, int lda, long zA,
              const f16* __restrict__ B, int ldb, long zB,
              const float* __restrict__ bias, int zBias,
              const float* __restrict__ res,
              float* __restrict__ C, f16* __restrict__ Ch, int ldc, int zC,
              int K, int relu)
{
    extern __shared__ char smem[];
    const uint32_t sb = smem_u32(smem);

    const int tid = threadIdx.x;
    const int l   = tid & 31;
    const int w   = tid >> 5;        // 0..15
    const int mw  = w >> 2;          // 0..3 : 32-row block
    const int nw  = w & 3;           // 0..3 : 32-col block
    const int m0  = blockIdx.y * 128;
    const int n0  = blockIdx.x * 128;
    const int z   = blockIdx.z;

    A += (long)z * zA;
    B += (long)z * zB;
    if (bias) bias += (long)z * zBias;
    const size_t cz = (size_t)z * zC;

    const uint32_t swz   = (uint32_t)((l & 7) << 4);
    const uint32_t ak    = (uint32_t)((l >> 4) << 4);
    const uint32_t bk    = (uint32_t)(((l >> 3) & 1) << 4);
    const uint32_t rowA  = (uint32_t)((mw * 32 + (l & 15)) * 128);
    const uint32_t rowB0 = (uint32_t)((nw * 32 + ((l >> 4) << 3) + (l & 7)) * 128);

    float acc[2][4][4];
#pragma unroll
    for (int i = 0; i < 2; i++)
#pragma unroll
        for (int j = 0; j < 4; j++)
#pragma unroll
            for (int q = 0; q < 4; q++) acc[i][j][q] = 0.f;

    const int NC = K >> 6;

    cpa_tile512(sb + A_OFF, A, lda, m0, 0, tid, 128);
    cpa_tile512(sb + B_OFF, B, ldb, n0, 0, tid, 128);
    CP_COMMIT();
    if (NC > 1) {
        cpa_tile512(sb + BUF_STRIDE + A_OFF, A, lda, m0, 64, tid, 128);
        cpa_tile512(sb + BUF_STRIDE + B_OFF, B, ldb, n0, 64, tid, 128);
        CP_COMMIT();
    }

    for (int c = 0; c < NC; c++) {
        const uint32_t bufb = sb + (c % 3) * BUF_STRIDE;

        if (c + 1 < NC) CP_WAIT1(); else CP_WAIT0();
        __syncthreads();

        if (c + 2 < NC) {
            const uint32_t bn = sb + ((c + 2) % 3) * BUF_STRIDE;
            cpa_tile512(bn + A_OFF, A, lda, m0, (c + 2) << 6, tid, 128);
            cpa_tile512(bn + B_OFF, B, ldb, n0, (c + 2) << 6, tid, 128);
            CP_COMMIT();
        }

#pragma unroll
        for (int kk = 0; kk < 4; kk++) {
            const uint32_t kbB = ((uint32_t)(kk * 32) | bk) ^ swz;
            const uint32_t kbA = ((uint32_t)(kk * 32) | ak) ^ swz;

            uint32_t bh[8];
            const uint32_t bB = bufb + B_OFF + rowB0 + kbB;
            ldsm4(bh + 0, bB);
            ldsm4(bh + 4, bB + 16 * 128);

            const uint32_t aB = bufb + A_OFF + rowA + kbA;
#pragma unroll
            for (int mt = 0; mt < 2; mt++) {
                uint32_t ah[4];
                ldsm4(ah, aB + mt * 2048);
#pragma unroll
                for (int nt = 0; nt < 4; nt++) mma16816(acc[mt][nt], ah, bh + nt * 2);
            }
        }
    }

    const int row_base = m0 + mw * 32 + (l >> 2);
    const int col_base = n0 + nw * 32 + 2 * (l & 3);
#pragma unroll
    for (int mt = 0; mt < 2; mt++) {
        const int row = row_base + mt * 16;
#pragma unroll
        for (int nt = 0; nt < 4; nt++) {
            const int col = col_base + nt * 8;
            float2 bv = bias ? *(const float2*)(bias + col) : make_float2(0.f, 0.f);
            float r[4];
            r[0] = acc[mt][nt][0] + bv.x;  r[1] = acc[mt][nt][1] + bv.y;
            r[2] = acc[mt][nt][2] + bv.x;  r[3] = acc[mt][nt][3] + bv.y;
            if (relu) {
#pragma unroll
                for (int q = 0; q < 4; q++) r[q] = fmaxf(r[q], 0.f);
            }
            if (res) {
                const float2 e0 = *(const float2*)(res + cz + (size_t)row * ldc + col);
                const float2 e1 = *(const float2*)(res + cz + (size_t)(row + 8) * ldc + col);
                r[0] += e0.x; r[1] += e0.y; r[2] += e1.x; r[3] += e1.y;
            }
            if (C) {
                *(float2*)(C + cz + (size_t)row * ldc + col)       = make_float2(r[0], r[1]);
                *(float2*)(C + cz + (size_t)(row + 8) * ldc + col) = make_float2(r[2], r[3]);
            }
            if (Ch) {
                __half2 h0 = __floats2half2_rn(r[0], r[1]);
                __half2 h1 = __floats2half2_rn(r[2], r[3]);
                *(__half2*)(Ch + cz + (size_t)row * ldc + col)       = h0;
                *(__half2*)(Ch + cz + (size_t)(row + 8) * ldc + col) = h1;
            }
        }
    }
}

// ---------------------------------------------------------------------------
// PERSISTENT Qt GEMM (R13): 2048 tiles, 296 CTAs, 3-stage across tiles.
// ---------------------------------------------------------------------------
#define QT_TILES 2048
#define QT_GRID  296

__global__ __launch_bounds__(256, 2)
void gemm_qt(const f16* __restrict__ Qp, const f16* __restrict__ wkT,
             f16* __restrict__ Qt)
{
    extern __shared__ char smem[];
    const uint32_t sb = smem_u32(smem);
    const int tid = threadIdx.x;
    const int l   = tid & 31;
    const int w   = tid >> 5;
    const int mw  = w >> 2;
    const int nw  = w & 3;
    const int bid = blockIdx.x;

    const uint32_t swz   = (uint32_t)((l & 7) << 4);
    const uint32_t ak    = (uint32_t)((l >> 4) << 4);
    const uint32_t bk    = (uint32_t)(((l >> 3) & 1) << 4);
    const uint32_t rowA  = (uint32_t)((mw * 64 + (l & 15)) * 128);
    const uint32_t rowB0 = (uint32_t)((nw * 32 + ((l >> 4) << 3) + (l & 7)) * 128);

    int nj = 0;
    for (int t = bid; t < QT_TILES; t += QT_GRID) nj++;
    if (nj == 0) return;

    {
        const int t0 = bid;
        cpa_tile(sb + A_OFF, Qp  + (size_t)((t0 >> 5) * 128) * 512 + (t0 & 7) * 64, 512, 0, 0, tid, 128);
        cpa_tile(sb + B_OFF, wkT + (size_t)(((t0 >> 3) & 3) * 128) * 512 + (t0 & 7) * 64, 512, 0, 0, tid, 128);
        CP_COMMIT();
    }
    if (nj > 1) {
        const int t1 = bid + QT_GRID;
        cpa_tile(sb + BUF_STRIDE + A_OFF, Qp  + (size_t)((t1 >> 5) * 128) * 512 + (t1 & 7) * 64, 512, 0, 0, tid, 128);
        cpa_tile(sb + BUF_STRIDE + B_OFF, wkT + (size_t)(((t1 >> 3) & 3) * 128) * 512 + (t1 & 7) * 64, 512, 0, 0, tid, 128);
        CP_COMMIT();
    }

    for (int j = 0; j < nj; j++) {
        const int t = bid + j * QT_GRID;
        const uint32_t bufb = sb + (j % 3) * BUF_STRIDE;

        if (j + 1 < nj) CP_WAIT1(); else CP_WAIT0();
        __syncthreads();

        if (j + 2 < nj) {
            const int tn = bid + (j + 2) * QT_GRID;
            const uint32_t bn = sb + ((j + 2) % 3) * BUF_STRIDE;
            cpa_tile(bn + A_OFF, Qp  + (size_t)((tn >> 5) * 128) * 512 + (tn & 7) * 64, 512, 0, 0, tid, 128);
            cpa_tile(bn + B_OFF, wkT + (size_t)(((tn >> 3) & 3) * 128) * 512 + (tn & 7) * 64, 512, 0, 0, tid, 128);
            CP_COMMIT();
        }

        float acc[4][4][4];
#pragma unroll
        for (int i = 0; i < 4; i++)
#pragma unroll
            for (int jj = 0; jj < 4; jj++)
#pragma unroll
                for (int q = 0; q < 4; q++) acc[i][jj][q] = 0.f;

#pragma unroll
        for (int kk = 0; kk < 4; kk++) {
            const uint32_t kbB = ((uint32_t)(kk * 32) | bk) ^ swz;
            const uint32_t kbA = ((uint32_t)(kk * 32) | ak) ^ swz;

            uint32_t bh[8];
            const uint32_t bB = bufb + B_OFF + rowB0 + kbB;
            ldsm4(bh + 0, bB);
            ldsm4(bh + 4, bB + 16 * 128);

            const uint32_t aB = bufb + A_OFF + rowA + kbA;
#pragma unroll
            for (int mt = 0; mt < 4; mt++) {
                uint32_t ah[4];
                ldsm4(ah, aB + mt * 2048);
#pragma unroll
                for (int nt = 0; nt < 4; nt++) mma16816(acc[mt][nt], ah, bh + nt * 2);
            }
        }

        const int h  = t & 7;
        const int n0 = ((t >> 3) & 3) * 128;
        const int m0 = (t >> 5) * 128;
        const int row_base = m0 + mw * 64 + (l >> 2);
        const int col_base = h * 512 + n0 + nw * 32 + 2 * (l & 3);
#pragma unroll
        for (int mt = 0; mt < 4; mt++) {
            const int row = row_base + mt * 16;
#pragma unroll
            for (int nt = 0; nt < 4; nt++) {
                const int col = col_base + nt * 8;
                __half2 h0 = __floats2half2_rn(acc[mt][nt][0], acc[mt][nt][1]);
                __half2 h1 = __floats2half2_rn(acc[mt][nt][2], acc[mt][nt][3]);
                *(__half2*)(Qt + (size_t)row * 4096 + col)       = h0;
                *(__half2*)(Qt + (size_t)(row + 8) * 4096 + col) = h1;
            }
        }
    }
}

// ---------------------------------------------------------------------------
// narrow GEMM (R13): BM=128, BN=64, per-head V-mix.
// ---------------------------------------------------------------------------
#define NA_OFF 0
#define NB_OFF 16384
#define NBUF_STRIDE 24576
#define SMEM_GEMM_N (3 * NBUF_STRIDE)

__global__ __launch_bounds__(256, 2)
void gemm_n64(const f16* __restrict__ A, int lda, long zA,
              const f16* __restrict__ B, int ldb, long zB,
              const float* __restrict__ bias, int zBias,
              f16* __restrict__ Ch, int ldc, int zC,
              int K)
{
    extern __shared__ char smem[];
    const uint32_t sb = smem_u32(smem);

    const int tid = threadIdx.x;
    const int l   = tid & 31;
    const int w   = tid >> 5;
    const int mw  = w >> 1;
    const int nw  = w & 1;
    const int m0  = blockIdx.y * 128;
    const int z   = blockIdx.z;

    A += (long)z * zA;
    B += (long)z * zB;
    bias += (long)z * zBias;
    const size_t cz = (size_t)z * zC;

    const uint32_t swz  = (uint32_t)((l & 7) << 4);
    const uint32_t ak   = (uint32_t)((l >> 4) << 4);
    const uint32_t bk   = (uint32_t)(((l >> 3) & 1) << 4);
    const uint32_t rowA = (uint32_t)((mw * 32 + (l & 15)) * 128);
    uint32_t rowB[2];
#pragma unroll
    for (int nt2 = 0; nt2 < 2; nt2++)
        rowB[nt2] = (uint32_t)((nw * 32 + nt2 * 16 + ((l >> 4) << 3) + (l & 7)) * 128);

    float acc[2][4][4];
#pragma unroll
    for (int i = 0; i < 2; i++)
#pragma unroll
        for (int j = 0; j < 4; j++)
#pragma unroll
            for (int q = 0; q < 4; q++) acc[i][j][q] = 0.f;

    const int NC = K >> 6;

    cpa_tile(sb + NA_OFF, A, lda, m0, 0, tid, 128);
    cpa_tile(sb + NB_OFF, B, ldb, 0,  0, tid, 64);
    CP_COMMIT();
    if (NC > 1) {
        cpa_tile(sb + NBUF_STRIDE + NA_OFF, A, lda, m0, 64, tid, 128);
        cpa_tile(sb + NBUF_STRIDE + NB_OFF, B, ldb, 0,  64, tid, 64);
        CP_COMMIT();
    }

    for (int c = 0; c < NC; c++) {
        const uint32_t bufb = sb + (c % 3) * NBUF_STRIDE;

        if (c + 1 < NC) CP_WAIT1(); else CP_WAIT0();
        __syncthreads();

        if (c + 2 < NC) {
            const uint32_t bn = sb + ((c + 2) % 3) * NBUF_STRIDE;
            cpa_tile(bn + NA_OFF, A, lda, m0, (c + 2) << 6, tid, 128);
            cpa_tile(bn + NB_OFF, B, ldb, 0,  (c + 2) << 6, tid, 64);
            CP_COMMIT();
        }

#pragma unroll
        for (int kk = 0; kk < 4; kk++) {
            const uint32_t kbB = ((uint32_t)(kk * 32) | bk) ^ swz;
            const uint32_t kbA = ((uint32_t)(kk * 32) | ak) ^ swz;

            uint32_t bh[8];
            ldsm4(bh + 0, bufb + NB_OFF + rowB[0] + kbB);
            ldsm4(bh + 4, bufb + NB_OFF + rowB[1] + kbB);

            const uint32_t aB = bufb + NA_OFF + rowA + kbA;
#pragma unroll
            for (int mt = 0; mt < 2; mt++) {
                uint32_t ah[4];
                ldsm4(ah, aB + mt * 2048);
#pragma unroll
                for (int nt = 0; nt < 4; nt++) mma16816(acc[mt][nt], ah, bh + nt * 2);
            }
        }
    }

    const int row_base = m0 + mw * 32 + (l >> 2);
    const int col_base = nw * 32 + 2 * (l & 3);
#pragma unroll
    for (int mt = 0; mt < 2; mt++) {
        const int row = row_base + mt * 16;
#pragma unroll
        for (int nt = 0; nt < 4; nt++) {
            const int col = col_base + nt * 8;
            const float2 bv = *(const float2*)(bias + col);
            __half2 h0 = __floats2half2_rn(acc[mt][nt][0] + bv.x, acc[mt][nt][1] + bv.y);
            __half2 h1 = __floats2half2_rn(acc[mt][nt][2] + bv.x, acc[mt][nt][3] + bv.y);
            *(__half2*)(Ch + cz + (size_t)row * ldc + col)       = h0;
            *(__half2*)(Ch + cz + (size_t)(row + 8) * ldc + col) = h1;
        }
    }
}

// ---------------------------------------------------------------------------
// Attention core (R13): block = query row m, warp = head h.
// ---------------------------------------------------------------------------
__global__ __launch_bounds__(256)
void attn_kernel(const f16* __restrict__ Qt, const float* __restrict__ key,
                 const float* __restrict__ value, f16* __restrict__ Y2)
{
    __shared__ float ks[8][512];
    __shared__ float vs[8][512];
    const int m = blockIdx.x;
    const int t = threadIdx.x;

    const float4* kg = (const float4*)(key   + (size_t)m * 8 * 512);
    const float4* vg = (const float4*)(value + (size_t)m * 8 * 512);
    float4* ksm = (float4*)ks;
    float4* vsm = (float4*)vs;
#pragma unroll
    for (int i = 0; i < 4; i++) {
        ksm[t + 256 * i] = kg[t + 256 * i];
        vsm[t + 256 * i] = vg[t + 256 * i];
    }
    __syncthreads();

    const int h = t >> 5, l = t & 31;

    const __half2* qtp = (const __half2*)(Qt + (size_t)m * 4096 + h * 512);
    float2 q2[8];
#pragma unroll
    for (int j = 0; j < 8; j++) q2[j] = __half22float2(qtp[l + 32 * j]);

    float s[8];
#pragma unroll
    for (int c = 0; c < 8; c++) {
        float p = 0.f;
#pragma unroll
        for (int j = 0; j < 8; j++) {
            const float2 kk = *(const float2*)&ks[c][64 * j + 2 * l];
            p += q2[j].x * kk.x + q2[j].y * kk.y;
        }
#pragma unroll
        for (int o = 16; o > 0; o >>= 1) p += __shfl_xor_sync(0xffffffffu, p, o);
        s[c] = p * 0.125f;
    }

    float mx = s[0];
#pragma unroll
    for (int c = 1; c < 8; c++) mx = fmaxf(mx, s[c]);
    float sum = 0.f;
#pragma unroll
    for (int c = 0; c < 8; c++) { s[c] = __expf(s[c] - mx); sum += s[c]; }
    const float inv = 1.f / sum;
#pragma unroll
    for (int c = 0; c < 8; c++) s[c] *= inv;

    __half2* yp = (__half2*)(Y2 + ((size_t)h * M_Q + m) * 512);
#pragma unroll
    for (int j = 0; j < 8; j++) {
        float2 a = make_float2(0.f, 0.f);
#pragma unroll
        for (int c = 0; c < 8; c++) {
            const float2 vv = *(const float2*)&vs[c][64 * j + 2 * l];
            a.x += s[c] * vv.x;
            a.y += s[c] * vv.y;
        }
        yp[l + 32 * j] = __floats2half2_rn(a.x, a.y);
    }
}

// ---------------------------------------------------------------------------
// LayerNorm(x), H=512, one block per row; optional fp16 copy.
// ---------------------------------------------------------------------------
__global__ __launch_bounds__(256)
void ln_residual_kernel(const float* __restrict__ x,
                        const float* __restrict__ g, const float* __restrict__ bt,
                        float* __restrict__ out, f16* __restrict__ oh)
{
    __shared__ float red[16];
    const int m = blockIdx.x;
    const int t = threadIdx.x;
    const int l = t & 31;
    const int w = t >> 5;
    const size_t base = (size_t)m * Hdim;

    const float s0 = x[base + t];
    const float s1 = x[base + t + 256];

    float v = s0 + s1;
#pragma unroll
    for (int o = 16; o > 0; o >>= 1) v += __shfl_xor_sync(0xffffffffu, v, o);
    if (l == 0) red[w] = v;
    __syncthreads();
    float mean = 0.f;
#pragma unroll
    for (int i = 0; i < 8; i++) mean += red[i];
    mean *= (1.f / 512.f);

    const float d0 = s0 - mean, d1 = s1 - mean;
    float vv = d0 * d0 + d1 * d1;
#pragma unroll
    for (int o = 16; o > 0; o >>= 1) vv += __shfl_xor_sync(0xffffffffu, vv, o);
    if (l == 0) red[8 + w] = vv;
    __syncthreads();
    float var = 0.f;
#pragma unroll
    for (int i = 0; i < 8; i++) var += red[8 + i];
    var *= (1.f / 512.f);
    const float rstd = rsqrtf(var + 1e-5f);

    const float y0 = d0 * rstd * g[t]       + bt[t];
    const float y1 = d1 * rstd * g[t + 256] + bt[t + 256];
    out[base + t]       = y0;
    out[base + t + 256] = y1;
    if (oh) {
        oh[base + t]       = __float2half_rn(y0);
        oh[base + t + 256] = __float2half_rn(y1);
    }
}

// ---------------------------------------------------------------------------
extern "C" void kernel_launch(void* const* d_in, const int* in_sizes, int n_in,
                              void* d_out, int out_size)
{
    (void)in_sizes; (void)n_in; (void)out_size;
    const float* query = (const float*)d_in[0];
    const float* key   = (const float*)d_in[1];
    const float* value = (const float*)d_in[2];
    const float* Wq    = (const float*)d_in[3];
    const float* bq    = (const float*)d_in[4];
    const float* Wk    = (const float*)d_in[5];
    const float* Wv    = (const float*)d_in[7];
    const float* bv    = (const float*)d_in[8];
    const float* Wo    = (const float*)d_in[9];
    const float* bo    = (const float*)d_in[10];
    const float* ln1g  = (const float*)d_in[11];
    const float* ln1b  = (const float*)d_in[12];
    const float* W1    = (const float*)d_in[13];
    const float* b1    = (const float*)d_in[14];
    const float* W2    = (const float*)d_in[15];
    const float* b2    = (const float*)d_in[16];
    const float* ln2g  = (const float*)d_in[17];
    const float* ln2b  = (const float*)d_in[18];
    float* out = (float*)d_out;

    float *x, *h1;
    cudaGetSymbolAddress((void**)&x,  g_x);
    cudaGetSymbolAddress((void**)&h1, g_h1);

    f16 *q16,*Qp,*Qt,*Y2,*x16,*h1h,*f1h;
    f16 *wq,*wkT,*wv,*wo,*w1,*w2;
    cudaGetSymbolAddress((void**)&q16, g_q16);
    cudaGetSymbolAddress((void**)&Qp,  g_Qp16);
    cudaGetSymbolAddress((void**)&Qt,  g_Qt);
    cudaGetSymbolAddress((void**)&Y2,  g_Y2);
    cudaGetSymbolAddress((void**)&x16, g_x16);
    cudaGetSymbolAddress((void**)&h1h, g_h1h);
    cudaGetSymbolAddress((void**)&f1h, g_f1h);
    cudaGetSymbolAddress((void**)&wq,  g_wq16);
    cudaGetSymbolAddress((void**)&wkT, g_wkT);
    cudaGetSymbolAddress((void**)&wv,  g_wv16);
    cudaGetSymbolAddress((void**)&wo,  g_wo16);
    cudaGetSymbolAddress((void**)&w1,  g_w116);
    cudaGetSymbolAddress((void**)&w2,  g_w216);

    cudaFuncSetAttribute(gemm_std, cudaFuncAttributeMaxDynamicSharedMemorySize, SMEM_GEMM);
    cudaFuncSetAttribute(gemm_qt,  cudaFuncAttributeMaxDynamicSharedMemorySize, SMEM_GEMM);
    cudaFuncSetAttribute(gemm_n64, cudaFuncAttributeMaxDynamicSharedMemorySize, SMEM_GEMM_N);

    // batched weight cvt (wq, wv, wo, w1, w2) in ONE launch
    {
        CvtTbl tbl;
        tbl.src[0] = (const float4*)Wq; tbl.dst[0] = (uint2*)wq;
        tbl.src[1] = (const float4*)Wv; tbl.dst[1] = (uint2*)wv;
        tbl.src[2] = (const float4*)Wo; tbl.dst[2] = (uint2*)wo;
        tbl.src[3] = (const float4*)W1; tbl.dst[3] = (uint2*)w1;
        tbl.src[4] = (const float4*)W2; tbl.dst[4] = (uint2*)w2;
        const int n0 = Hdim*Hdim/4, n1 = HF*Hdim/4;
        tbl.cum[0] = n0; tbl.cum[1] = 2*n0; tbl.cum[2] = 3*n0;
        tbl.cum[3] = 3*n0 + n1; tbl.cum[4] = 3*n0 + 2*n1;
        tbl.njobs = 5;
        cvt_batch<<<(tbl.cum[4] + 255)/256, 256>>>(tbl);
    }
    cvt_t16<<<dim3(16, 16), 256>>>(Wk, wkT, Hdim, Hdim);
    cvt_h16<<<(M_Q*Hdim/4 + 255)/256, 256>>>((const float4*)query, (uint2*)q16, M_Q*Hdim/4);

    // Qp = q16 @ Wq^T + bq  (fp16)
    gemm_std<<<dim3(4, 64, 1), 512, SMEM_GEMM>>>(
        q16, Hdim, 0, wq, Hdim, 0, bq, 0, 0, 0, Qp, Hdim, 0, Hdim, 0);

    // Qt (persistent, 2048 tiles)
    gemm_qt<<<QT_GRID, 256, SMEM_GEMM>>>(Qp, wkT, Qt);

    // attention
    attn_kernel<<<M_Q, 256>>>(Qt, key, value, Y2);

    // x16_h = Y2_h @ Wv_h^T + bv_h
    gemm_n64<<<dim3(1, 64, 8), 256, SMEM_GEMM_N>>>(
        Y2, Hdim, (long)M_Q*Hdim, wv, Hdim, (long)64*Hdim, bv, 64,
        x16, Hdim, 64, Hdim);

    // O projection + query residual (fused) -> x ; LN1 -> h1 (+fp16)
    gemm_std<<<dim3(4, 64, 1), 512, SMEM_GEMM>>>(
        x16, Hdim, 0, wo, Hdim, 0, bo, 0, query, x, 0, Hdim, 0, Hdim, 0);
    ln_residual_kernel<<<M_Q, 256>>>(x, ln1g, ln1b, h1, h1h);

    // FFN1 (relu, fp16) -> FFN2 + h1 residual (fused) -> x ; LN2 -> out
    gemm_std<<<dim3(8, 64, 1), 512, SMEM_GEMM>>>(
        h1h, Hdim, 0, w1, Hdim, 0, b1, 0, 0, 0, f1h, HF, 0, Hdim, 1);
    gemm_std<<<dim3(4, 64, 1), 512, SMEM_GEMM>>>(
        f1h, HF, 0, w2, HF, 0, b2, 0, h1, x, 0, Hdim, 0, HF, 0);
    ln_residual_kernel<<<M_Q, 256>>>(x, ln2g, ln2b, out, 0);
}

// round 17
// speedup vs baseline: 1.0692x; 1.0692x over previous
#include <cuda_runtime.h>
#include <cuda_fp16.h>
#include <cstdint>

// ---------------------------------------------------------------------------
// AttentionEncoderLayer: B=4, C=8, F=2048, H=512, NH=8, dh=64, Hf=1024
// Folded attention algebra (softmax shift-invariance + linearity):
//   scores: s_h[m,c] = (Qp_h[m] @ Wk_h) . k[8m+c]        (bk drops out)
//   values: x_h[m]   = (sum_c att_c v[8m+c]) @ Wv_h^T    (bv -> output bias)
// GEMMs: 1-pass fp16 HMMA (fp32 accum), occ-2 tile 128x128 warp 64x32
// (confirmed local optimum: both bigger-tile/fewer-warps and smaller-tile/
// more-warps variants measured worse). Kernels byte-identical to R13 best.
// This round: Programmatic Dependent Launch (PSS) on the 12-kernel chain to
// overlap launch/prologue with predecessor drain.
// ---------------------------------------------------------------------------

#define M_Q   8192
#define Hdim  512
#define HF    1024

typedef __half f16;

#if defined(__CUDA_ARCH__) && (__CUDA_ARCH__ >= 900)
#define GRID_DEP_SYNC() cudaGridDependencySynchronize()
#else
#define GRID_DEP_SYNC()
#endif

// fp32 spine
__device__ float g_x  [M_Q * Hdim];
__device__ float g_h1 [M_Q * Hdim];

// fp16 buffers
__device__ f16 g_q16 [M_Q * Hdim];
__device__ f16 g_Qp16[M_Q * Hdim];
__device__ f16 g_Qt  [M_Q * 8 * Hdim];     // [m, h*512+d]
__device__ f16 g_Y2  [8 * M_Q * Hdim];     // [h*8192+m, d]
__device__ f16 g_x16 [M_Q * Hdim];
__device__ f16 g_h1h [M_Q * Hdim];
__device__ f16 g_f1h [M_Q * HF  ];
__device__ f16 g_wq16[Hdim * Hdim];
__device__ f16 g_wkT [Hdim * Hdim];        // Wk transposed
__device__ f16 g_wv16[Hdim * Hdim];
__device__ f16 g_wo16[Hdim * Hdim];
__device__ f16 g_w116[HF * Hdim];
__device__ f16 g_w216[Hdim * HF];

// ---------------- helpers ----------------
__device__ __forceinline__ uint32_t smem_u32(const void* p) {
    uint32_t a;
    asm("{ .reg .u64 t; cvta.to.shared.u64 t, %1; cvt.u32.u64 %0, t; }" : "=r"(a) : "l"(p));
    return a;
}
__device__ __forceinline__ void ldsm4(uint32_t* r, uint32_t addr) {
    asm volatile("ldmatrix.sync.aligned.m8n8.x4.shared.b16 {%0,%1,%2,%3}, [%4];"
                 : "=r"(r[0]), "=r"(r[1]), "=r"(r[2]), "=r"(r[3]) : "r"(addr));
}
__device__ __forceinline__ void mma16816(float* d, const uint32_t* a, const uint32_t* b) {
    asm volatile("mma.sync.aligned.m16n8k16.row.col.f32.f16.f16.f32 "
                 "{%0,%1,%2,%3}, {%4,%5,%6,%7}, {%8,%9}, {%0,%1,%2,%3};"
                 : "+f"(d[0]), "+f"(d[1]), "+f"(d[2]), "+f"(d[3])
                 : "r"(a[0]), "r"(a[1]), "r"(a[2]), "r"(a[3]), "r"(b[0]), "r"(b[1]));
}
__device__ __forceinline__ void cp16(uint32_t dst, const void* src) {
    asm volatile("cp.async.cg.shared.global [%0], [%1], 16;" :: "r"(dst), "l"(src));
}
#define CP_COMMIT() asm volatile("cp.async.commit_group;" ::: "memory")
#define CP_WAIT1()  asm volatile("cp.async.wait_group 1;" ::: "memory")
#define CP_WAIT0()  asm volatile("cp.async.wait_group 0;" ::: "memory")

// ---------------------------------------------------------------------------
// prepass: fp32 -> fp16 (R13 layout: 5-job weight batch + plain query cvt)
// ---------------------------------------------------------------------------
struct CvtTbl {
    const float4* src[6];
    uint2*        dst[6];
    int           cum[6];
    int           njobs;
};

__global__ __launch_bounds__(256)
void cvt_batch(CvtTbl tbl)
{
    int i = blockIdx.x * 256 + threadIdx.x;
    if (i >= tbl.cum[tbl.njobs - 1]) return;
    int j = 0;
#pragma unroll
    for (int q = 0; q < 5; q++) if (j < tbl.njobs - 1 && i >= tbl.cum[j]) j++;
    const int base = (j == 0) ? 0 : tbl.cum[j - 1];
    const int idx = i - base;
    const float4 x = tbl.src[j][idx];
    __half2 h01 = __floats2half2_rn(x.x, x.y);
    __half2 h23 = __floats2half2_rn(x.z, x.w);
    tbl.dst[j][idx] = make_uint2(*(uint32_t*)&h01, *(uint32_t*)&h23);
}

__global__ __launch_bounds__(256)
void cvt_h16(const float4* __restrict__ src, uint2* __restrict__ hi, int n4)
{
    const int i = blockIdx.x * 256 + threadIdx.x;
    if (i >= n4) return;
    const float4 x = src[i];
    __half2 h01 = __floats2half2_rn(x.x, x.y);
    __half2 h23 = __floats2half2_rn(x.z, x.w);
    hi[i] = make_uint2(*(uint32_t*)&h01, *(uint32_t*)&h23);
}

// dst[c, r] = src[r, c]
__global__ __launch_bounds__(256)
void cvt_t16(const float* __restrict__ src, f16* __restrict__ dst, int R, int C)
{
    __shared__ float t[32][33];
    const int bi = blockIdx.x * 32, bj = blockIdx.y * 32;
    const int tx = threadIdx.x & 31, ty = threadIdx.x >> 5;
#pragma unroll
    for (int i = 0; i < 32; i += 8)
        t[ty + i][tx] = src[(size_t)(bi + ty + i) * C + bj + tx];
    __syncthreads();
#pragma unroll
    for (int i = 0; i < 32; i += 8)
        dst[(size_t)(bj + ty + i) * R + bi + tx] = __float2half_rn(t[tx][ty + i]);
}

// ---------------------------------------------------------------------------
// tile copier (swizzled, 16B cp.async)
// ---------------------------------------------------------------------------
#define A_OFF 0
#define B_OFF 16384
#define BUF_STRIDE 32768
#define SMEM_GEMM (3 * BUF_STRIDE)   // 98304

__device__ __forceinline__ void cpa_tile(uint32_t dst, const f16* __restrict__ src,
                                         int ldk, int row0, int k0, int tid, int nrows)
{
    const int s  = tid & 7;
    const int r0 = tid >> 3;
    const char* g = (const char*)(src + (size_t)(row0 + r0) * ldk + k0) + s * 16;
    const uint32_t d0 = dst + r0 * 128 + ((s * 16) ^ ((r0 & 7) << 4));
    const size_t gs = (size_t)32 * ldk * 2;
#pragma unroll
    for (int i = 0; i < nrows / 32; i++)
        cp16(d0 + i * 32 * 128, g + i * gs);
}

// ---------------------------------------------------------------------------
// std GEMM (R13): BM=128 BN=128 BK=64, warp 64x32, 3-stage, occ 2.
// ---------------------------------------------------------------------------
__global__ __launch_bounds__(256, 2)
void gemm_std(const f16* __restrict__ A, int lda, long zA,
              const f16* __restrict__ B, int ldb, long zB,
              const float* __restrict__ bias, int zBias,
              const float* __restrict__ res,
              float* __restrict__ C, f16* __restrict__ Ch, int ldc, int zC,
              int K, int relu)
{
    GRID_DEP_SYNC();
    extern __shared__ char smem[];
    const uint32_t sb = smem_u32(smem);

    const int tid = threadIdx.x;
    const int l   = tid & 31;
    const int w   = tid >> 5;
    const int mw  = w >> 2;
    const int nw  = w & 3;
    const int m0  = blockIdx.y * 128;
    const int n0  = blockIdx.x * 128;
    const int z   = blockIdx.z;

    A += (long)z * zA;
    B += (long)z * zB;
    if (bias) bias += (long)z * zBias;
    const size_t cz = (size_t)z * zC;

    const uint32_t swz   = (uint32_t)((l & 7) << 4);
    const uint32_t ak    = (uint32_t)((l >> 4) << 4);
    const uint32_t bk    = (uint32_t)(((l >> 3) & 1) << 4);
    const uint32_t rowA  = (uint32_t)((mw * 64 + (l & 15)) * 128);
    const uint32_t rowB0 = (uint32_t)((nw * 32 + ((l >> 4) << 3) + (l & 7)) * 128);

    float acc[4][4][4];
#pragma unroll
    for (int i = 0; i < 4; i++)
#pragma unroll
        for (int j = 0; j < 4; j++)
#pragma unroll
            for (int q = 0; q < 4; q++) acc[i][j][q] = 0.f;

    const int NC = K >> 6;

    cpa_tile(sb + A_OFF, A, lda, m0, 0, tid, 128);
    cpa_tile(sb + B_OFF, B, ldb, n0, 0, tid, 128);
    CP_COMMIT();
    if (NC > 1) {
        cpa_tile(sb + BUF_STRIDE + A_OFF, A, lda, m0, 64, tid, 128);
        cpa_tile(sb + BUF_STRIDE + B_OFF, B, ldb, n0, 64, tid, 128);
        CP_COMMIT();
    }

    for (int c = 0; c < NC; c++) {
        const uint32_t bufb = sb + (c % 3) * BUF_STRIDE;

        if (c + 1 < NC) CP_WAIT1(); else CP_WAIT0();
        __syncthreads();

        if (c + 2 < NC) {
            const uint32_t bn = sb + ((c + 2) % 3) * BUF_STRIDE;
            cpa_tile(bn + A_OFF, A, lda, m0, (c + 2) << 6, tid, 128);
            cpa_tile(bn + B_OFF, B, ldb, n0, (c + 2) << 6, tid, 128);
            CP_COMMIT();
        }

#pragma unroll
        for (int kk = 0; kk < 4; kk++) {
            const uint32_t kbB = ((uint32_t)(kk * 32) | bk) ^ swz;
            const uint32_t kbA = ((uint32_t)(kk * 32) | ak) ^ swz;

            uint32_t bh[8];
            const uint32_t bB = bufb + B_OFF + rowB0 + kbB;
            ldsm4(bh + 0, bB);
            ldsm4(bh + 4, bB + 16 * 128);

            const uint32_t aB = bufb + A_OFF + rowA + kbA;
#pragma unroll
            for (int mt = 0; mt < 4; mt++) {
                uint32_t ah[4];
                ldsm4(ah, aB + mt * 2048);
#pragma unroll
                for (int nt = 0; nt < 4; nt++) mma16816(acc[mt][nt], ah, bh + nt * 2);
            }
        }
    }

    const int row_base = m0 + mw * 64 + (l >> 2);
    const int col_base = n0 + nw * 32 + 2 * (l & 3);
#pragma unroll
    for (int mt = 0; mt < 4; mt++) {
        const int row = row_base + mt * 16;
#pragma unroll
        for (int nt = 0; nt < 4; nt++) {
            const int col = col_base + nt * 8;
            float2 bv = bias ? *(const float2*)(bias + col) : make_float2(0.f, 0.f);
            float r[4];
            r[0] = acc[mt][nt][0] + bv.x;  r[1] = acc[mt][nt][1] + bv.y;
            r[2] = acc[mt][nt][2] + bv.x;  r[3] = acc[mt][nt][3] + bv.y;
            if (relu) {
#pragma unroll
                for (int q = 0; q < 4; q++) r[q] = fmaxf(r[q], 0.f);
            }
            if (res) {
                const float2 e0 = *(const float2*)(res + cz + (size_t)row * ldc + col);
                const float2 e1 = *(const float2*)(res + cz + (size_t)(row + 8) * ldc + col);
                r[0] += e0.x; r[1] += e0.y; r[2] += e1.x; r[3] += e1.y;
            }
            if (C) {
                *(float2*)(C + cz + (size_t)row * ldc + col)       = make_float2(r[0], r[1]);
                *(float2*)(C + cz + (size_t)(row + 8) * ldc + col) = make_float2(r[2], r[3]);
            }
            if (Ch) {
                __half2 h0 = __floats2half2_rn(r[0], r[1]);
                __half2 h1 = __floats2half2_rn(r[2], r[3]);
                *(__half2*)(Ch + cz + (size_t)row * ldc + col)       = h0;
                *(__half2*)(Ch + cz + (size_t)(row + 8) * ldc + col) = h1;
            }
        }
    }
}

// ---------------------------------------------------------------------------
// PERSISTENT Qt GEMM (R13): 2048 tiles, 296 CTAs, 3-stage across tiles.
// ---------------------------------------------------------------------------
#define QT_TILES 2048
#define QT_GRID  296

__global__ __launch_bounds__(256, 2)
void gemm_qt(const f16* __restrict__ Qp, const f16* __restrict__ wkT,
             f16* __restrict__ Qt)
{
    GRID_DEP_SYNC();
    extern __shared__ char smem[];
    const uint32_t sb = smem_u32(smem);
    const int tid = threadIdx.x;
    const int l   = tid & 31;
    const int w   = tid >> 5;
    const int mw  = w >> 2;
    const int nw  = w & 3;
    const int bid = blockIdx.x;

    const uint32_t swz   = (uint32_t)((l & 7) << 4);
    const uint32_t ak    = (uint32_t)((l >> 4) << 4);
    const uint32_t bk    = (uint32_t)(((l >> 3) & 1) << 4);
    const uint32_t rowA  = (uint32_t)((mw * 64 + (l & 15)) * 128);
    const uint32_t rowB0 = (uint32_t)((nw * 32 + ((l >> 4) << 3) + (l & 7)) * 128);

    int nj = 0;
    for (int t = bid; t < QT_TILES; t += QT_GRID) nj++;
    if (nj == 0) return;

    {
        const int t0 = bid;
        cpa_tile(sb + A_OFF, Qp  + (size_t)((t0 >> 5) * 128) * 512 + (t0 & 7) * 64, 512, 0, 0, tid, 128);
        cpa_tile(sb + B_OFF, wkT + (size_t)(((t0 >> 3) & 3) * 128) * 512 + (t0 & 7) * 64, 512, 0, 0, tid, 128);
        CP_COMMIT();
    }
    if (nj > 1) {
        const int t1 = bid + QT_GRID;
        cpa_tile(sb + BUF_STRIDE + A_OFF, Qp  + (size_t)((t1 >> 5) * 128) * 512 + (t1 & 7) * 64, 512, 0, 0, tid, 128);
        cpa_tile(sb + BUF_STRIDE + B_OFF, wkT + (size_t)(((t1 >> 3) & 3) * 128) * 512 + (t1 & 7) * 64, 512, 0, 0, tid, 128);
        CP_COMMIT();
    }

    for (int j = 0; j < nj; j++) {
        const int t = bid + j * QT_GRID;
        const uint32_t bufb = sb + (j % 3) * BUF_STRIDE;

        if (j + 1 < nj) CP_WAIT1(); else CP_WAIT0();
        __syncthreads();

        if (j + 2 < nj) {
            const int tn = bid + (j + 2) * QT_GRID;
            const uint32_t bn = sb + ((j + 2) % 3) * BUF_STRIDE;
            cpa_tile(bn + A_OFF, Qp  + (size_t)((tn >> 5) * 128) * 512 + (tn & 7) * 64, 512, 0, 0, tid, 128);
            cpa_tile(bn + B_OFF, wkT + (size_t)(((tn >> 3) & 3) * 128) * 512 + (tn & 7) * 64, 512, 0, 0, tid, 128);
            CP_COMMIT();
        }

        float acc[4][4][4];
#pragma unroll
        for (int i = 0; i < 4; i++)
#pragma unroll
            for (int jj = 0; jj < 4; jj++)
#pragma unroll
                for (int q = 0; q < 4; q++) acc[i][jj][q] = 0.f;

#pragma unroll
        for (int kk = 0; kk < 4; kk++) {
            const uint32_t kbB = ((uint32_t)(kk * 32) | bk) ^ swz;
            const uint32_t kbA = ((uint32_t)(kk * 32) | ak) ^ swz;

            uint32_t bh[8];
            const uint32_t bB = bufb + B_OFF + rowB0 + kbB;
            ldsm4(bh + 0, bB);
            ldsm4(bh + 4, bB + 16 * 128);

            const uint32_t aB = bufb + A_OFF + rowA + kbA;
#pragma unroll
            for (int mt = 0; mt < 4; mt++) {
                uint32_t ah[4];
                ldsm4(ah, aB + mt * 2048);
#pragma unroll
                for (int nt = 0; nt < 4; nt++) mma16816(acc[mt][nt], ah, bh + nt * 2);
            }
        }

        const int h  = t & 7;
        const int n0 = ((t >> 3) & 3) * 128;
        const int m0 = (t >> 5) * 128;
        const int row_base = m0 + mw * 64 + (l >> 2);
        const int col_base = h * 512 + n0 + nw * 32 + 2 * (l & 3);
#pragma unroll
        for (int mt = 0; mt < 4; mt++) {
            const int row = row_base + mt * 16;
#pragma unroll
            for (int nt = 0; nt < 4; nt++) {
                const int col = col_base + nt * 8;
                __half2 h0 = __floats2half2_rn(acc[mt][nt][0], acc[mt][nt][1]);
                __half2 h1 = __floats2half2_rn(acc[mt][nt][2], acc[mt][nt][3]);
                *(__half2*)(Qt + (size_t)row * 4096 + col)       = h0;
                *(__half2*)(Qt + (size_t)(row + 8) * 4096 + col) = h1;
            }
        }
    }
}

// ---------------------------------------------------------------------------
// narrow GEMM (R13): BM=128, BN=64, per-head V-mix.
// ---------------------------------------------------------------------------
#define NA_OFF 0
#define NB_OFF 16384
#define NBUF_STRIDE 24576
#define SMEM_GEMM_N (3 * NBUF_STRIDE)

__global__ __launch_bounds__(256, 2)
void gemm_n64(const f16* __restrict__ A, int lda, long zA,
              const f16* __restrict__ B, int ldb, long zB,
              const float* __restrict__ bias, int zBias,
              f16* __restrict__ Ch, int ldc, int zC,
              int K)
{
    GRID_DEP_SYNC();
    extern __shared__ char smem[];
    const uint32_t sb = smem_u32(smem);

    const int tid = threadIdx.x;
    const int l   = tid & 31;
    const int w   = tid >> 5;
    const int mw  = w >> 1;
    const int nw  = w & 1;
    const int m0  = blockIdx.y * 128;
    const int z   = blockIdx.z;

    A += (long)z * zA;
    B += (long)z * zB;
    bias += (long)z * zBias;
    const size_t cz = (size_t)z * zC;

    const uint32_t swz  = (uint32_t)((l & 7) << 4);
    const uint32_t ak   = (uint32_t)((l >> 4) << 4);
    const uint32_t bk   = (uint32_t)(((l >> 3) & 1) << 4);
    const uint32_t rowA = (uint32_t)((mw * 32 + (l & 15)) * 128);
    uint32_t rowB[2];
#pragma unroll
    for (int nt2 = 0; nt2 < 2; nt2++)
        rowB[nt2] = (uint32_t)((nw * 32 + nt2 * 16 + ((l >> 4) << 3) + (l & 7)) * 128);

    float acc[2][4][4];
#pragma unroll
    for (int i = 0; i < 2; i++)
#pragma unroll
        for (int j = 0; j < 4; j++)
#pragma unroll
            for (int q = 0; q < 4; q++) acc[i][j][q] = 0.f;

    const int NC = K >> 6;

    cpa_tile(sb + NA_OFF, A, lda, m0, 0, tid, 128);
    cpa_tile(sb + NB_OFF, B, ldb, 0,  0, tid, 64);
    CP_COMMIT();
    if (NC > 1) {
        cpa_tile(sb + NBUF_STRIDE + NA_OFF, A, lda, m0, 64, tid, 128);
        cpa_tile(sb + NBUF_STRIDE + NB_OFF, B, ldb, 0,  64, tid, 64);
        CP_COMMIT();
    }

    for (int c = 0; c < NC; c++) {
        const uint32_t bufb = sb + (c % 3) * NBUF_STRIDE;

        if (c + 1 < NC) CP_WAIT1(); else CP_WAIT0();
        __syncthreads();

        if (c + 2 < NC) {
            const uint32_t bn = sb + ((c + 2) % 3) * NBUF_STRIDE;
            cpa_tile(bn + NA_OFF, A, lda, m0, (c + 2) << 6, tid, 128);
            cpa_tile(bn + NB_OFF, B, ldb, 0,  (c + 2) << 6, tid, 64);
            CP_COMMIT();
        }

#pragma unroll
        for (int kk = 0; kk < 4; kk++) {
            const uint32_t kbB = ((uint32_t)(kk * 32) | bk) ^ swz;
            const uint32_t kbA = ((uint32_t)(kk * 32) | ak) ^ swz;

            uint32_t bh[8];
            ldsm4(bh + 0, bufb + NB_OFF + rowB[0] + kbB);
            ldsm4(bh + 4, bufb + NB_OFF + rowB[1] + kbB);

            const uint32_t aB = bufb + NA_OFF + rowA + kbA;
#pragma unroll
            for (int mt = 0; mt < 2; mt++) {
                uint32_t ah[4];
                ldsm4(ah, aB + mt * 2048);
#pragma unroll
                for (int nt = 0; nt < 4; nt++) mma16816(acc[mt][nt], ah, bh + nt * 2);
            }
        }
    }

    const int row_base = m0 + mw * 32 + (l >> 2);
    const int col_base = nw * 32 + 2 * (l & 3);
#pragma unroll
    for (int mt = 0; mt < 2; mt++) {
        const int row = row_base + mt * 16;
#pragma unroll
        for (int nt = 0; nt < 4; nt++) {
            const int col = col_base + nt * 8;
            const float2 bv = *(const float2*)(bias + col);
            __half2 h0 = __floats2half2_rn(acc[mt][nt][0] + bv.x, acc[mt][nt][1] + bv.y);
            __half2 h1 = __floats2half2_rn(acc[mt][nt][2] + bv.x, acc[mt][nt][3] + bv.y);
            *(__half2*)(Ch + cz + (size_t)row * ldc + col)       = h0;
            *(__half2*)(Ch + cz + (size_t)(row + 8) * ldc + col) = h1;
        }
    }
}

// ---------------------------------------------------------------------------
// Attention core (R13): block = query row m, warp = head h.
// ---------------------------------------------------------------------------
__global__ __launch_bounds__(256)
void attn_kernel(const f16* __restrict__ Qt, const float* __restrict__ key,
                 const float* __restrict__ value, f16* __restrict__ Y2)
{
    GRID_DEP_SYNC();
    __shared__ float ks[8][512];
    __shared__ float vs[8][512];
    const int m = blockIdx.x;
    const int t = threadIdx.x;

    const float4* kg = (const float4*)(key   + (size_t)m * 8 * 512);
    const float4* vg = (const float4*)(value + (size_t)m * 8 * 512);
    float4* ksm = (float4*)ks;
    float4* vsm = (float4*)vs;
#pragma unroll
    for (int i = 0; i < 4; i++) {
        ksm[t + 256 * i] = kg[t + 256 * i];
        vsm[t + 256 * i] = vg[t + 256 * i];
    }
    __syncthreads();

    const int h = t >> 5, l = t & 31;

    const __half2* qtp = (const __half2*)(Qt + (size_t)m * 4096 + h * 512);
    float2 q2[8];
#pragma unroll
    for (int j = 0; j < 8; j++) q2[j] = __half22float2(qtp[l + 32 * j]);

    float s[8];
#pragma unroll
    for (int c = 0; c < 8; c++) {
        float p = 0.f;
#pragma unroll
        for (int j = 0; j < 8; j++) {
            const float2 kk = *(const float2*)&ks[c][64 * j + 2 * l];
            p += q2[j].x * kk.x + q2[j].y * kk.y;
        }
#pragma unroll
        for (int o = 16; o > 0; o >>= 1) p += __shfl_xor_sync(0xffffffffu, p, o);
        s[c] = p * 0.125f;
    }

    float mx = s[0];
#pragma unroll
    for (int c = 1; c < 8; c++) mx = fmaxf(mx, s[c]);
    float sum = 0.f;
#pragma unroll
    for (int c = 0; c < 8; c++) { s[c] = __expf(s[c] - mx); sum += s[c]; }
    const float inv = 1.f / sum;
#pragma unroll
    for (int c = 0; c < 8; c++) s[c] *= inv;

    __half2* yp = (__half2*)(Y2 + ((size_t)h * M_Q + m) * 512);
#pragma unroll
    for (int j = 0; j < 8; j++) {
        float2 a = make_float2(0.f, 0.f);
#pragma unroll
        for (int c = 0; c < 8; c++) {
            const float2 vv = *(const float2*)&vs[c][64 * j + 2 * l];
            a.x += s[c] * vv.x;
            a.y += s[c] * vv.y;
        }
        yp[l + 32 * j] = __floats2half2_rn(a.x, a.y);
    }
}

// ---------------------------------------------------------------------------
// LayerNorm(x), H=512, one block per row; optional fp16 copy.
// ---------------------------------------------------------------------------
__global__ __launch_bounds__(256)
void ln_residual_kernel(const float* __restrict__ x,
                        const float* __restrict__ g, const float* __restrict__ bt,
                        float* __restrict__ out, f16* __restrict__ oh)
{
    GRID_DEP_SYNC();
    __shared__ float red[16];
    const int m = blockIdx.x;
    const int t = threadIdx.x;
    const int l = t & 31;
    const int w = t >> 5;
    const size_t base = (size_t)m * Hdim;

    const float s0 = x[base + t];
    const float s1 = x[base + t + 256];

    float v = s0 + s1;
#pragma unroll
    for (int o = 16; o > 0; o >>= 1) v += __shfl_xor_sync(0xffffffffu, v, o);
    if (l == 0) red[w] = v;
    __syncthreads();
    float mean = 0.f;
#pragma unroll
    for (int i = 0; i < 8; i++) mean += red[i];
    mean *= (1.f / 512.f);

    const float d0 = s0 - mean, d1 = s1 - mean;
    float vv = d0 * d0 + d1 * d1;
#pragma unroll
    for (int o = 16; o > 0; o >>= 1) vv += __shfl_xor_sync(0xffffffffu, vv, o);
    if (l == 0) red[8 + w] = vv;
    __syncthreads();
    float var = 0.f;
#pragma unroll
    for (int i = 0; i < 8; i++) var += red[8 + i];
    var *= (1.f / 512.f);
    const float rstd = rsqrtf(var + 1e-5f);

    const float y0 = d0 * rstd * g[t]       + bt[t];
    const float y1 = d1 * rstd * g[t + 256] + bt[t + 256];
    out[base + t]       = y0;
    out[base + t + 256] = y1;
    if (oh) {
        oh[base + t]       = __float2half_rn(y0);
        oh[base + t + 256] = __float2half_rn(y1);
    }
}

// ---------------------------------------------------------------------------
// host-side PDL launch helper
// ---------------------------------------------------------------------------
template <typename Kern, typename... Args>
static inline void launch_pdl(Kern k, dim3 grid, dim3 block, size_t smem, Args... args)
{
    cudaLaunchAttribute attr[1];
    attr[0].id = cudaLaunchAttributeProgrammaticStreamSerialization;
    attr[0].val.programmaticStreamSerializationAllowed = 1;
    cudaLaunchConfig_t cfg;
    cfg.gridDim = grid;
    cfg.blockDim = block;
    cfg.dynamicSmemBytes = smem;
    cfg.stream = 0;
    cfg.attrs = attr;
    cfg.numAttrs = 1;
    cudaLaunchKernelEx(&cfg, k, args...);
}

// ---------------------------------------------------------------------------
extern "C" void kernel_launch(void* const* d_in, const int* in_sizes, int n_in,
                              void* d_out, int out_size)
{
    (void)in_sizes; (void)n_in; (void)out_size;
    const float* query = (const float*)d_in[0];
    const float* key   = (const float*)d_in[1];
    const float* value = (const float*)d_in[2];
    const float* Wq    = (const float*)d_in[3];
    const float* bq    = (const float*)d_in[4];
    const float* Wk    = (const float*)d_in[5];
    const float* Wv    = (const float*)d_in[7];
    const float* bv    = (const float*)d_in[8];
    const float* Wo    = (const float*)d_in[9];
    const float* bo    = (const float*)d_in[10];
    const float* ln1g  = (const float*)d_in[11];
    const float* ln1b  = (const float*)d_in[12];
    const float* W1    = (const float*)d_in[13];
    const float* b1    = (const float*)d_in[14];
    const float* W2    = (const float*)d_in[15];
    const float* b2    = (const float*)d_in[16];
    const float* ln2g  = (const float*)d_in[17];
    const float* ln2b  = (const float*)d_in[18];
    float* out = (float*)d_out;

    float *x, *h1;
    cudaGetSymbolAddress((void**)&x,  g_x);
    cudaGetSymbolAddress((void**)&h1, g_h1);

    f16 *q16,*Qp,*Qt,*Y2,*x16,*h1h,*f1h;
    f16 *wq,*wkT,*wv,*wo,*w1,*w2;
    cudaGetSymbolAddress((void**)&q16, g_q16);
    cudaGetSymbolAddress((void**)&Qp,  g_Qp16);
    cudaGetSymbolAddress((void**)&Qt,  g_Qt);
    cudaGetSymbolAddress((void**)&Y2,  g_Y2);
    cudaGetSymbolAddress((void**)&x16, g_x16);
    cudaGetSymbolAddress((void**)&h1h, g_h1h);
    cudaGetSymbolAddress((void**)&f1h, g_f1h);
    cudaGetSymbolAddress((void**)&wq,  g_wq16);
    cudaGetSymbolAddress((void**)&wkT, g_wkT);
    cudaGetSymbolAddress((void**)&wv,  g_wv16);
    cudaGetSymbolAddress((void**)&wo,  g_wo16);
    cudaGetSymbolAddress((void**)&w1,  g_w116);
    cudaGetSymbolAddress((void**)&w2,  g_w216);

    cudaFuncSetAttribute(gemm_std, cudaFuncAttributeMaxDynamicSharedMemorySize, SMEM_GEMM);
    cudaFuncSetAttribute(gemm_qt,  cudaFuncAttributeMaxDynamicSharedMemorySize, SMEM_GEMM);
    cudaFuncSetAttribute(gemm_n64, cudaFuncAttributeMaxDynamicSharedMemorySize, SMEM_GEMM_N);

    // batched weight cvt (wq, wv, wo, w1, w2) in ONE launch
    {
        CvtTbl tbl;
        tbl.src[0] = (const float4*)Wq; tbl.dst[0] = (uint2*)wq;
        tbl.src[1] = (const float4*)Wv; tbl.dst[1] = (uint2*)wv;
        tbl.src[2] = (const float4*)Wo; tbl.dst[2] = (uint2*)wo;
        tbl.src[3] = (const float4*)W1; tbl.dst[3] = (uint2*)w1;
        tbl.src[4] = (const float4*)W2; tbl.dst[4] = (uint2*)w2;
        const int n0 = Hdim*Hdim/4, n1 = HF*Hdim/4;
        tbl.cum[0] = n0; tbl.cum[1] = 2*n0; tbl.cum[2] = 3*n0;
        tbl.cum[3] = 3*n0 + n1; tbl.cum[4] = 3*n0 + 2*n1;
        tbl.njobs = 5;
        cvt_batch<<<(tbl.cum[4] + 255)/256, 256>>>(tbl);
    }
    launch_pdl(cvt_t16, dim3(16, 16), dim3(256), 0, Wk, wkT, Hdim, Hdim);
    launch_pdl(cvt_h16, dim3(M_Q*Hdim/4/256), dim3(256), 0,
               (const float4*)query, (uint2*)q16, M_Q*Hdim/4);

    // Qp = q16 @ Wq^T + bq  (fp16)
    launch_pdl(gemm_std, dim3(4, 64, 1), dim3(256), (size_t)SMEM_GEMM,
               q16, Hdim, 0L, wq, Hdim, 0L, bq, 0, (const float*)0,
               (float*)0, Qp, Hdim, 0, Hdim, 0);

    // Qt (persistent, 2048 tiles)
    launch_pdl(gemm_qt, dim3(QT_GRID), dim3(256), (size_t)SMEM_GEMM, Qp, wkT, Qt);

    // attention
    launch_pdl(attn_kernel, dim3(M_Q), dim3(256), 0, Qt, key, value, Y2);

    // x16_h = Y2_h @ Wv_h^T + bv_h
    launch_pdl(gemm_n64, dim3(1, 64, 8), dim3(256), (size_t)SMEM_GEMM_N,
               Y2, Hdim, (long)M_Q*Hdim, wv, Hdim, (long)64*Hdim, bv, 64,
               x16, Hdim, 64, Hdim);

    // O projection + query residual (fused) -> x ; LN1 -> h1 (+fp16)
    launch_pdl(gemm_std, dim3(4, 64, 1), dim3(256), (size_t)SMEM_GEMM,
               x16, Hdim, 0L, wo, Hdim, 0L, bo, 0, query,
               x, (f16*)0, Hdim, 0, Hdim, 0);
    launch_pdl(ln_residual_kernel, dim3(M_Q), dim3(256), 0, x, ln1g, ln1b, h1, h1h);

    // FFN1 (relu, fp16) -> FFN2 + h1 residual (fused) -> x ; LN2 -> out
    launch_pdl(gemm_std, dim3(8, 64, 1), dim3(256), (size_t)SMEM_GEMM,
               h1h, Hdim, 0L, w1, Hdim, 0L, b1, 0, (const float*)0,
               (float*)0, f1h, HF, 0, Hdim, 1);
    launch_pdl(gemm_std, dim3(4, 64, 1), dim3(256), (size_t)SMEM_GEMM,
               f1h, HF, 0L, w2, HF, 0L, b2, 0, h1,
               x, (f16*)0, Hdim, 0, HF, 0);
    launch_pdl(ln_residual_kernel, dim3(M_Q), dim3(256), 0, x, ln2g, ln2b, out, (f16*)0);
}